// round 3
// baseline (speedup 1.0000x reference)
#include <cuda_runtime.h>
#include <math.h>

#define H      450
#define NMESS  6000
#define NNODES 4000
#define KNEI   6
#define BATCH  256
#define DEPTH  15

// ---------------- scratch (device globals; no allocation allowed) ----------
__device__ float g_X    [NMESS * H];
__device__ float g_XZ   [NMESS * H];
__device__ float g_XR   [NMESS * H];
__device__ float g_XH   [NMESS * H];
__device__ float g_Hb0  [NMESS * H];
__device__ float g_Hb1  [NMESS * H];
__device__ float g_HU   [NMESS * H];
__device__ float g_SUMH [NMESS * H];
__device__ float g_SUMGH[NMESS * H];
__device__ float g_Z    [NMESS * H];
__device__ float g_RV   [BATCH * 2 * H];
__device__ float g_B1   [BATCH * H];
__device__ float g_B2   [BATCH * H];

__device__ __forceinline__ float sigmoidf_(float v) {
    return 1.0f / (1.0f + __expf(-v));
}

// ---------------- generic NT GEMM: C[m,n] = sum_k A[m,k] * W[n,k] ----------
// MODE 0: C = acc (+ bias[n])
// MODE 1: C = sigmoid(add[idx] + acc)                       (z gate)
// MODE 2: pre = tanh(add[idx] + acc);
//         C = (m==0) ? 0 : (1-z[idx])*sumh[idx] + z[idx]*pre (h update + mask)
// MODE 3: C = leaky_relu(acc + bias[n], 0.1)
template <int MODE>
__global__ void gemm_nt(const float* __restrict__ A, int lda,
                        const float* __restrict__ W, int ldb,
                        float* __restrict__ C, int ldc,
                        int M, int N, int Kd,
                        const float* __restrict__ bias,
                        const float* __restrict__ add,
                        const float* __restrict__ zb,
                        const float* __restrict__ sumh)
{
    constexpr int BM = 64, BN = 64, BK = 16;
    __shared__ float As[BK][BM];
    __shared__ float Bs[BK][BN];

    const int tid = threadIdx.x;          // 256 threads
    const int tx = tid & 15;              // 0..15
    const int ty = tid >> 4;              // 0..15
    const int row0 = blockIdx.y * BM;
    const int col0 = blockIdx.x * BN;

    float acc[4][4] = {};

    for (int k0 = 0; k0 < Kd; k0 += BK) {
        #pragma unroll
        for (int i = 0; i < 4; i++) {
            int e = tid + i * 256;
            int r = e / BK, c = e % BK;
            int gr = row0 + r, gc = k0 + c;
            As[c][r] = (gr < M && gc < Kd) ? A[(size_t)gr * lda + gc] : 0.0f;
        }
        #pragma unroll
        for (int i = 0; i < 4; i++) {
            int e = tid + i * 256;
            int r = e / BK, c = e % BK;
            int gr = col0 + r, gc = k0 + c;
            Bs[c][r] = (gr < N && gc < Kd) ? W[(size_t)gr * ldb + gc] : 0.0f;
        }
        __syncthreads();

        #pragma unroll
        for (int k = 0; k < BK; k++) {
            float4 a4 = *(const float4*)&As[k][ty * 4];
            float4 b4 = *(const float4*)&Bs[k][tx * 4];
            float av[4] = {a4.x, a4.y, a4.z, a4.w};
            float bv[4] = {b4.x, b4.y, b4.z, b4.w};
            #pragma unroll
            for (int i = 0; i < 4; i++)
                #pragma unroll
                for (int j = 0; j < 4; j++)
                    acc[i][j] = fmaf(av[i], bv[j], acc[i][j]);
        }
        __syncthreads();
    }

    #pragma unroll
    for (int i = 0; i < 4; i++) {
        int m = row0 + ty * 4 + i;
        if (m >= M) continue;
        #pragma unroll
        for (int j = 0; j < 4; j++) {
            int n = col0 + tx * 4 + j;
            if (n >= N) continue;
            size_t idx = (size_t)m * ldc + n;
            float v = acc[i][j];
            if (MODE == 0) {
                if (bias) v += bias[n];
                C[idx] = v;
            } else if (MODE == 1) {
                C[idx] = sigmoidf_(add[idx] + v);
            } else if (MODE == 2) {
                float pre = tanhf(add[idx] + v);
                float zz  = zb[idx];
                float hv  = (1.0f - zz) * sumh[idx] + zz * pre;
                C[idx] = (m == 0) ? 0.0f : hv;
            } else {
                v += bias[n];
                C[idx] = (v > 0.0f) ? v : 0.1f * v;
            }
        }
    }
}

// ---------------- small kernels ---------------------------------------------
__global__ void zero_k(float* p, int n) {
    int i = blockIdx.x * blockDim.x + threadIdx.x;
    if (i < n) p[i] = 0.0f;
}

// X[m,:] = emb[fnode[fmess[m]], :]
__global__ void gather_x(const int* __restrict__ fmess, const int* __restrict__ fnode,
                         const float* __restrict__ emb, float* __restrict__ X)
{
    int m = blockIdx.x;
    __shared__ int src;
    if (threadIdx.x == 0) src = fnode[fmess[m]];
    __syncthreads();
    for (int j = threadIdx.x; j < H; j += blockDim.x)
        X[(size_t)m * H + j] = emb[(size_t)src * H + j];
}

// sum_h[m,:] = sum_k h[mess_graph[m,k], :]
__global__ void gather_sum_h(const int* __restrict__ mg, const float* __restrict__ h,
                             float* __restrict__ out)
{
    int m = blockIdx.x;
    __shared__ int idx[KNEI];
    if (threadIdx.x < KNEI) idx[threadIdx.x] = mg[m * KNEI + threadIdx.x];
    __syncthreads();
    for (int j = threadIdx.x; j < H; j += blockDim.x) {
        float s = 0.0f;
        #pragma unroll
        for (int k = 0; k < KNEI; k++) s += h[(size_t)idx[k] * H + j];
        out[(size_t)m * H + j] = s;
    }
}

// sum_gh[m,:] = sum_k sigmoid(xr[m,:] + Urb + hU[g_k,:]) * h[g_k,:]
__global__ void gather_sum_gh(const int* __restrict__ mg, const float* __restrict__ h,
                              const float* __restrict__ hU, const float* __restrict__ xr,
                              const float* __restrict__ urb, float* __restrict__ out)
{
    int m = blockIdx.x;
    __shared__ int idx[KNEI];
    if (threadIdx.x < KNEI) idx[threadIdx.x] = mg[m * KNEI + threadIdx.x];
    __syncthreads();
    for (int j = threadIdx.x; j < H; j += blockDim.x) {
        float base = xr[(size_t)m * H + j] + urb[j];
        float s = 0.0f;
        #pragma unroll
        for (int k = 0; k < KNEI; k++) {
            int g = idx[k];
            float r = sigmoidf_(base + hU[(size_t)g * H + j]);
            s += r * h[(size_t)g * H + j];
        }
        out[(size_t)m * H + j] = s;
    }
}

// rv[b, 0:H]  = emb[fnode[root], :]
// rv[b, H:2H] = sum_k h[node_graph[root,k], :]
__global__ void root_vecs(const int* __restrict__ root_idx, const int* __restrict__ fnode,
                          const int* __restrict__ ng, const float* __restrict__ emb,
                          const float* __restrict__ h, float* __restrict__ rv)
{
    int b = blockIdx.x;
    __shared__ int node;
    __shared__ int idx[KNEI];
    if (threadIdx.x == 0) {
        int r = root_idx[b];
        node = fnode[r];
        #pragma unroll
        for (int k = 0; k < KNEI; k++) idx[k] = ng[r * KNEI + k];
    }
    __syncthreads();
    for (int j = threadIdx.x; j < H; j += blockDim.x) {
        rv[(size_t)b * 2 * H + j] = emb[(size_t)node * H + j];
        float s = 0.0f;
        #pragma unroll
        for (int k = 0; k < KNEI; k++) s += h[(size_t)idx[k] * H + j];
        rv[(size_t)b * 2 * H + H + j] = s;
    }
}

// out[b] = dot(h2[b,:], d3w) + d3b
__global__ void score_k(const float* __restrict__ h2, const float* __restrict__ w,
                        const float* __restrict__ b, float* __restrict__ out)
{
    int bb = blockIdx.x;
    float s = 0.0f;
    for (int j = threadIdx.x; j < H; j += blockDim.x)
        s += h2[(size_t)bb * H + j] * w[j];
    #pragma unroll
    for (int o = 16; o > 0; o >>= 1) s += __shfl_down_sync(0xffffffffu, s, o);
    __shared__ float red[8];
    if ((threadIdx.x & 31) == 0) red[threadIdx.x >> 5] = s;
    __syncthreads();
    if (threadIdx.x < 8) {
        s = red[threadIdx.x];
        #pragma unroll
        for (int o = 4; o > 0; o >>= 1) s += __shfl_down_sync(0xffu, s, o);
        if (threadIdx.x == 0) out[bb] = s + b[0];
    }
}

// ---------------- launch -----------------------------------------------------
extern "C" void kernel_launch(void* const* d_in, const int* in_sizes, int n_in,
                              void* d_out, int out_size)
{
    const int*   fnode = (const int*)  d_in[0];
    const int*   fmess = (const int*)  d_in[1];
    const int*   ng    = (const int*)  d_in[2];
    const int*   mg    = (const int*)  d_in[3];
    const int*   root  = (const int*)  d_in[4];
    const float* emb   = (const float*)d_in[5];
    const float* Wz    = (const float*)d_in[6];   // [450, 900]
    const float* Wzb   = (const float*)d_in[7];
    const float* Wr    = (const float*)d_in[8];   // [450, 450]
    const float* Ur    = (const float*)d_in[9];   // [450, 450]
    const float* Urb   = (const float*)d_in[10];
    const float* Wh    = (const float*)d_in[11];  // [450, 900]
    const float* Whb   = (const float*)d_in[12];
    const float* D1w   = (const float*)d_in[13];  // [450, 900]
    const float* D1b   = (const float*)d_in[14];
    const float* D2w   = (const float*)d_in[15];  // [450, 450]
    const float* D2b   = (const float*)d_in[16];
    const float* D3w   = (const float*)d_in[17];  // [450]
    const float* D3b   = (const float*)d_in[18];
    float* out = (float*)d_out;
    (void)in_sizes; (void)n_in; (void)out_size;   // depth fixed at 15 by problem spec

    float *X, *XZ, *XR, *XH, *Hb0, *Hb1, *HU, *SUMH, *SUMGH, *Z, *RV, *B1, *B2;
    cudaGetSymbolAddress((void**)&X,     g_X);
    cudaGetSymbolAddress((void**)&XZ,    g_XZ);
    cudaGetSymbolAddress((void**)&XR,    g_XR);
    cudaGetSymbolAddress((void**)&XH,    g_XH);
    cudaGetSymbolAddress((void**)&Hb0,   g_Hb0);
    cudaGetSymbolAddress((void**)&Hb1,   g_Hb1);
    cudaGetSymbolAddress((void**)&HU,    g_HU);
    cudaGetSymbolAddress((void**)&SUMH,  g_SUMH);
    cudaGetSymbolAddress((void**)&SUMGH, g_SUMGH);
    cudaGetSymbolAddress((void**)&Z,     g_Z);
    cudaGetSymbolAddress((void**)&RV,    g_RV);
    cudaGetSymbolAddress((void**)&B1,    g_B1);
    cudaGetSymbolAddress((void**)&B2,    g_B2);

    const int MH = NMESS * H;
    dim3 gMain((H + 63) / 64, (NMESS + 63) / 64);   // 8 x 94
    dim3 gD   ((H + 63) / 64, (BATCH + 63) / 64);   // 8 x 4

    // h0 = 0
    zero_k<<<(MH + 255) / 256, 256>>>(Hb0, MH);

    // x = emb[fnode[fmess]]
    gather_x<<<NMESS, 256>>>(fmess, fnode, emb, X);

    // loop-invariant x-projections
    gemm_nt<0><<<gMain, 256>>>(X, H, Wz,       2 * H, XZ, H, NMESS, H, H, Wzb, nullptr, nullptr, nullptr);
    gemm_nt<0><<<gMain, 256>>>(X, H, Wr,           H, XR, H, NMESS, H, H, nullptr, nullptr, nullptr, nullptr);
    gemm_nt<0><<<gMain, 256>>>(X, H, Wh,       2 * H, XH, H, NMESS, H, H, Whb, nullptr, nullptr, nullptr);

    for (int it = 0; it < DEPTH; it++) {
        float* hin  = (it & 1) ? Hb1 : Hb0;
        float* hout = (it & 1) ? Hb0 : Hb1;

        gather_sum_h<<<NMESS, 256>>>(mg, hin, SUMH);
        gemm_nt<0><<<gMain, 256>>>(hin,  H, Ur,          H, HU,   H, NMESS, H, H, nullptr, nullptr, nullptr, nullptr);
        gemm_nt<1><<<gMain, 256>>>(SUMH, H, Wz + H,  2 * H, Z,    H, NMESS, H, H, nullptr, XZ, nullptr, nullptr);
        gather_sum_gh<<<NMESS, 256>>>(mg, hin, HU, XR, Urb, SUMGH);
        gemm_nt<2><<<gMain, 256>>>(SUMGH, H, Wh + H, 2 * H, hout, H, NMESS, H, H, nullptr, XH, Z, SUMH);
    }
    float* hfinal = Hb1;  // DEPTH=15 (odd): last write lands in Hb1

    root_vecs<<<BATCH, 256>>>(root, fnode, ng, emb, hfinal, RV);

    gemm_nt<3><<<gD, 256>>>(RV, 2 * H, D1w, 2 * H, B1, H, BATCH, H, 2 * H, D1b, nullptr, nullptr, nullptr);
    gemm_nt<3><<<gD, 256>>>(B1, H,     D2w,     H, B2, H, BATCH, H,     H, D2b, nullptr, nullptr, nullptr);
    score_k<<<BATCH, 256>>>(B2, D3w, D3b, out);
}

// round 4
// speedup vs baseline: 1.0037x; 1.0037x over previous
#include <cuda_runtime.h>
#include <math.h>

#define H      450
#define NMESS  6000
#define NNODES 4000
#define KNEI   6
#define BATCH  256
#define DEPTH  15

// ---------------- scratch (device globals; no allocation allowed) ----------
__device__ float g_X    [NMESS * H];
__device__ float g_XZ   [NMESS * H];
__device__ float g_XR   [NMESS * H];
__device__ float g_XH   [NMESS * H];
__device__ float g_Hb0  [NMESS * H];
__device__ float g_Hb1  [NMESS * H];
__device__ float g_HU   [NMESS * H];
__device__ float g_SUMH [NMESS * H];
__device__ float g_SUMGH[NMESS * H];
__device__ float g_Z    [NMESS * H];
__device__ float g_RV   [BATCH * 2 * H];
__device__ float g_B1   [BATCH * H];
__device__ float g_B2   [BATCH * H];

__device__ __forceinline__ float sigmoidf_(float v) {
    return 1.0f / (1.0f + __expf(-v));
}

// ---------------- generic NT GEMM: C[m,n] = sum_k A[m,k] * W[n,k] ----------
// MODE 0: C = acc (+ bias[n])
// MODE 1: C = sigmoid(add[idx] + acc)                       (z gate)
// MODE 2: pre = tanh(add[idx] + acc);
//         C = (m==0) ? 0 : (1-z[idx])*sumh[idx] + z[idx]*pre (h update + mask)
// MODE 3: C = leaky_relu(acc + bias[n], 0.1)
template <int MODE>
__global__ void gemm_nt(const float* __restrict__ A, int lda,
                        const float* __restrict__ W, int ldb,
                        float* __restrict__ C, int ldc,
                        int M, int N, int Kd,
                        const float* __restrict__ bias,
                        const float* __restrict__ add,
                        const float* __restrict__ zb,
                        const float* __restrict__ sumh)
{
    constexpr int BM = 64, BN = 64, BK = 16;
    __shared__ float As[BK][BM];
    __shared__ float Bs[BK][BN];

    const int tid = threadIdx.x;          // 256 threads
    const int tx = tid & 15;              // 0..15
    const int ty = tid >> 4;              // 0..15
    const int row0 = blockIdx.y * BM;
    const int col0 = blockIdx.x * BN;

    float acc[4][4] = {};

    for (int k0 = 0; k0 < Kd; k0 += BK) {
        #pragma unroll
        for (int i = 0; i < 4; i++) {
            int e = tid + i * 256;
            int r = e / BK, c = e % BK;
            int gr = row0 + r, gc = k0 + c;
            As[c][r] = (gr < M && gc < Kd) ? A[(size_t)gr * lda + gc] : 0.0f;
        }
        #pragma unroll
        for (int i = 0; i < 4; i++) {
            int e = tid + i * 256;
            int r = e / BK, c = e % BK;
            int gr = col0 + r, gc = k0 + c;
            Bs[c][r] = (gr < N && gc < Kd) ? W[(size_t)gr * ldb + gc] : 0.0f;
        }
        __syncthreads();

        #pragma unroll
        for (int k = 0; k < BK; k++) {
            float4 a4 = *(const float4*)&As[k][ty * 4];
            float4 b4 = *(const float4*)&Bs[k][tx * 4];
            float av[4] = {a4.x, a4.y, a4.z, a4.w};
            float bv[4] = {b4.x, b4.y, b4.z, b4.w};
            #pragma unroll
            for (int i = 0; i < 4; i++)
                #pragma unroll
                for (int j = 0; j < 4; j++)
                    acc[i][j] = fmaf(av[i], bv[j], acc[i][j]);
        }
        __syncthreads();
    }

    #pragma unroll
    for (int i = 0; i < 4; i++) {
        int m = row0 + ty * 4 + i;
        if (m >= M) continue;
        #pragma unroll
        for (int j = 0; j < 4; j++) {
            int n = col0 + tx * 4 + j;
            if (n >= N) continue;
            size_t idx = (size_t)m * ldc + n;
            float v = acc[i][j];
            if (MODE == 0) {
                if (bias) v += bias[n];
                C[idx] = v;
            } else if (MODE == 1) {
                C[idx] = sigmoidf_(add[idx] + v);
            } else if (MODE == 2) {
                float pre = tanhf(add[idx] + v);
                float zz  = zb[idx];
                float hv  = (1.0f - zz) * sumh[idx] + zz * pre;
                C[idx] = (m == 0) ? 0.0f : hv;
            } else {
                v += bias[n];
                C[idx] = (v > 0.0f) ? v : 0.1f * v;
            }
        }
    }
}

// ---------------- small kernels ---------------------------------------------
__global__ void zero_k(float* p, int n) {
    int i = blockIdx.x * blockDim.x + threadIdx.x;
    if (i < n) p[i] = 0.0f;
}

// X[m,:] = emb[fnode[fmess[m]], :]
__global__ void gather_x(const int* __restrict__ fmess, const int* __restrict__ fnode,
                         const float* __restrict__ emb, float* __restrict__ X)
{
    int m = blockIdx.x;
    __shared__ int src;
    if (threadIdx.x == 0) src = fnode[fmess[m]];
    __syncthreads();
    for (int j = threadIdx.x; j < H; j += blockDim.x)
        X[(size_t)m * H + j] = emb[(size_t)src * H + j];
}

// sum_h[m,:] = sum_k h[mess_graph[m,k], :]
__global__ void gather_sum_h(const int* __restrict__ mg, const float* __restrict__ h,
                             float* __restrict__ out)
{
    int m = blockIdx.x;
    __shared__ int idx[KNEI];
    if (threadIdx.x < KNEI) idx[threadIdx.x] = mg[m * KNEI + threadIdx.x];
    __syncthreads();
    for (int j = threadIdx.x; j < H; j += blockDim.x) {
        float s = 0.0f;
        #pragma unroll
        for (int k = 0; k < KNEI; k++) s += h[(size_t)idx[k] * H + j];
        out[(size_t)m * H + j] = s;
    }
}

// sum_gh[m,:] = sum_k sigmoid(xr[m,:] + Urb + hU[g_k,:]) * h[g_k,:]
__global__ void gather_sum_gh(const int* __restrict__ mg, const float* __restrict__ h,
                              const float* __restrict__ hU, const float* __restrict__ xr,
                              const float* __restrict__ urb, float* __restrict__ out)
{
    int m = blockIdx.x;
    __shared__ int idx[KNEI];
    if (threadIdx.x < KNEI) idx[threadIdx.x] = mg[m * KNEI + threadIdx.x];
    __syncthreads();
    for (int j = threadIdx.x; j < H; j += blockDim.x) {
        float base = xr[(size_t)m * H + j] + urb[j];
        float s = 0.0f;
        #pragma unroll
        for (int k = 0; k < KNEI; k++) {
            int g = idx[k];
            float r = sigmoidf_(base + hU[(size_t)g * H + j]);
            s += r * h[(size_t)g * H + j];
        }
        out[(size_t)m * H + j] = s;
    }
}

// rv[b, 0:H]  = emb[fnode[root], :]
// rv[b, H:2H] = sum_k h[node_graph[root,k], :]
__global__ void root_vecs(const int* __restrict__ root_idx, const int* __restrict__ fnode,
                          const int* __restrict__ ng, const float* __restrict__ emb,
                          const float* __restrict__ h, float* __restrict__ rv)
{
    int b = blockIdx.x;
    __shared__ int node;
    __shared__ int idx[KNEI];
    if (threadIdx.x == 0) {
        int r = root_idx[b];
        node = fnode[r];
        #pragma unroll
        for (int k = 0; k < KNEI; k++) idx[k] = ng[r * KNEI + k];
    }
    __syncthreads();
    for (int j = threadIdx.x; j < H; j += blockDim.x) {
        rv[(size_t)b * 2 * H + j] = emb[(size_t)node * H + j];
        float s = 0.0f;
        #pragma unroll
        for (int k = 0; k < KNEI; k++) s += h[(size_t)idx[k] * H + j];
        rv[(size_t)b * 2 * H + H + j] = s;
    }
}

// out[b] = dot(h2[b,:], d3w) + d3b
__global__ void score_k(const float* __restrict__ h2, const float* __restrict__ w,
                        const float* __restrict__ b, float* __restrict__ out)
{
    int bb = blockIdx.x;
    float s = 0.0f;
    for (int j = threadIdx.x; j < H; j += blockDim.x)
        s += h2[(size_t)bb * H + j] * w[j];
    #pragma unroll
    for (int o = 16; o > 0; o >>= 1) s += __shfl_down_sync(0xffffffffu, s, o);
    __shared__ float red[8];
    if ((threadIdx.x & 31) == 0) red[threadIdx.x >> 5] = s;
    __syncthreads();
    if (threadIdx.x < 8) {
        s = red[threadIdx.x];
        #pragma unroll
        for (int o = 4; o > 0; o >>= 1) s += __shfl_down_sync(0xffu, s, o);
        if (threadIdx.x == 0) out[bb] = s + b[0];
    }
}

// ---------------- launch -----------------------------------------------------
extern "C" void kernel_launch(void* const* d_in, const int* in_sizes, int n_in,
                              void* d_out, int out_size)
{
    const int*   fnode = (const int*)  d_in[0];
    const int*   fmess = (const int*)  d_in[1];
    const int*   ng    = (const int*)  d_in[2];
    const int*   mg    = (const int*)  d_in[3];
    const int*   root  = (const int*)  d_in[4];
    const float* emb   = (const float*)d_in[5];
    const float* Wz    = (const float*)d_in[6];   // [450, 900]
    const float* Wzb   = (const float*)d_in[7];
    const float* Wr    = (const float*)d_in[8];   // [450, 450]
    const float* Ur    = (const float*)d_in[9];   // [450, 450]
    const float* Urb   = (const float*)d_in[10];
    const float* Wh    = (const float*)d_in[11];  // [450, 900]
    const float* Whb   = (const float*)d_in[12];
    const float* D1w   = (const float*)d_in[13];  // [450, 900]
    const float* D1b   = (const float*)d_in[14];
    const float* D2w   = (const float*)d_in[15];  // [450, 450]
    const float* D2b   = (const float*)d_in[16];
    const float* D3w   = (const float*)d_in[17];  // [450]
    const float* D3b   = (const float*)d_in[18];
    float* out = (float*)d_out;
    (void)in_sizes; (void)n_in; (void)out_size;   // depth fixed at 15 by problem spec

    float *X, *XZ, *XR, *XH, *Hb0, *Hb1, *HU, *SUMH, *SUMGH, *Z, *RV, *B1, *B2;
    cudaGetSymbolAddress((void**)&X,     g_X);
    cudaGetSymbolAddress((void**)&XZ,    g_XZ);
    cudaGetSymbolAddress((void**)&XR,    g_XR);
    cudaGetSymbolAddress((void**)&XH,    g_XH);
    cudaGetSymbolAddress((void**)&Hb0,   g_Hb0);
    cudaGetSymbolAddress((void**)&Hb1,   g_Hb1);
    cudaGetSymbolAddress((void**)&HU,    g_HU);
    cudaGetSymbolAddress((void**)&SUMH,  g_SUMH);
    cudaGetSymbolAddress((void**)&SUMGH, g_SUMGH);
    cudaGetSymbolAddress((void**)&Z,     g_Z);
    cudaGetSymbolAddress((void**)&RV,    g_RV);
    cudaGetSymbolAddress((void**)&B1,    g_B1);
    cudaGetSymbolAddress((void**)&B2,    g_B2);

    const int MH = NMESS * H;
    dim3 gMain((H + 63) / 64, (NMESS + 63) / 64);   // 8 x 94
    dim3 gD   ((H + 63) / 64, (BATCH + 63) / 64);   // 8 x 4

    // h0 = 0
    zero_k<<<(MH + 255) / 256, 256>>>(Hb0, MH);

    // x = emb[fnode[fmess]]
    gather_x<<<NMESS, 256>>>(fmess, fnode, emb, X);

    // loop-invariant x-projections
    gemm_nt<0><<<gMain, 256>>>(X, H, Wz,       2 * H, XZ, H, NMESS, H, H, Wzb, nullptr, nullptr, nullptr);
    gemm_nt<0><<<gMain, 256>>>(X, H, Wr,           H, XR, H, NMESS, H, H, nullptr, nullptr, nullptr, nullptr);
    gemm_nt<0><<<gMain, 256>>>(X, H, Wh,       2 * H, XH, H, NMESS, H, H, Whb, nullptr, nullptr, nullptr);

    for (int it = 0; it < DEPTH; it++) {
        float* hin  = (it & 1) ? Hb1 : Hb0;
        float* hout = (it & 1) ? Hb0 : Hb1;

        gather_sum_h<<<NMESS, 256>>>(mg, hin, SUMH);
        gemm_nt<0><<<gMain, 256>>>(hin,  H, Ur,          H, HU,   H, NMESS, H, H, nullptr, nullptr, nullptr, nullptr);
        gemm_nt<1><<<gMain, 256>>>(SUMH, H, Wz + H,  2 * H, Z,    H, NMESS, H, H, nullptr, XZ, nullptr, nullptr);
        gather_sum_gh<<<NMESS, 256>>>(mg, hin, HU, XR, Urb, SUMGH);
        gemm_nt<2><<<gMain, 256>>>(SUMGH, H, Wh + H, 2 * H, hout, H, NMESS, H, H, nullptr, XH, Z, SUMH);
    }
    float* hfinal = Hb1;  // DEPTH=15 (odd): last write lands in Hb1

    root_vecs<<<BATCH, 256>>>(root, fnode, ng, emb, hfinal, RV);

    gemm_nt<3><<<gD, 256>>>(RV, 2 * H, D1w, 2 * H, B1, H, BATCH, H, 2 * H, D1b, nullptr, nullptr, nullptr);
    gemm_nt<3><<<gD, 256>>>(B1, H,     D2w,     H, B2, H, BATCH, H,     H, D2b, nullptr, nullptr, nullptr);
    score_k<<<BATCH, 256>>>(B2, D3w, D3b, out);
}